// round 9
// baseline (speedup 1.0000x reference)
#include <cuda_runtime.h>
#include <cuda_fp16.h>
#include <math.h>
#include <cstdint>

#define NN 100000
#define EE 1600000
#define DD 128
#define NROWS4 ((NN * DD) / 4)

// ---------------- scratch (static device globals; no allocation) -------------
__device__ __align__(16) __half g_t0[NN * DD];     // activation ping (starts as x)
__device__ __align__(16) __half g_t1[NN * DD];     // activation pong

__device__ int   g_col[EE];
__device__ int   g_cnt[NN];          // zero-initialized; re-zeroed by k_scan3b
__device__ int   g_rowptr[NN + 1];
__device__ int   g_wcur[NN];
__device__ float g_invdeg[NN];
__device__ int   g_tmp[NN];
__device__ int   g_bsum[128];
__device__ int   g_is64;

// transposed fp16 weights per layer: [n=128][k=256]
__device__ __align__(16) __half g_wt[3][128 * 256];

// ================= helpers =====================================================
__device__ __forceinline__ uint32_t smem_u32(const void* p) {
    uint32_t a;
    asm("{ .reg .u64 t; cvta.to.shared.u64 t, %1; cvt.u32.u64 %0, t; }" : "=r"(a) : "l"(p));
    return a;
}
__device__ __forceinline__ void ldm_x4(uint32_t* r, uint32_t addr) {
    asm volatile("ldmatrix.sync.aligned.m8n8.x4.shared.b16 {%0,%1,%2,%3}, [%4];"
                 : "=r"(r[0]), "=r"(r[1]), "=r"(r[2]), "=r"(r[3]) : "r"(addr));
}
__device__ __forceinline__ void mma16816(float* c, const uint32_t* a, uint32_t b0, uint32_t b1) {
    asm volatile(
        "mma.sync.aligned.m16n8k16.row.col.f32.f16.f16.f32 "
        "{%0,%1,%2,%3},{%4,%5,%6,%7},{%8,%9},{%0,%1,%2,%3};"
        : "+f"(c[0]), "+f"(c[1]), "+f"(c[2]), "+f"(c[3])
        : "r"(a[0]), "r"(a[1]), "r"(a[2]), "r"(a[3]), "r"(b0), "r"(b1));
}
__device__ __forceinline__ void cp_async16z(uint32_t dst, const void* src, int ok) {
    asm volatile("cp.async.cg.shared.global [%0], [%1], 16, %2;"
                 :: "r"(dst), "l"(src), "r"(ok ? 16 : 0) : "memory");
}
__device__ __forceinline__ uint32_t packh2(float a, float b) {
    __half2 h = __floats2half2_rn(a, b);
    return *(uint32_t*)&h;
}

// ---------------- fused init: x -> fp16 convert + degree histogram -------------
__global__ void k_inithist(const float* __restrict__ x, const void* __restrict__ ei) {
    __shared__ int is64s;
    if (threadIdx.x < 32) {
        const long long* p = (const long long*)ei;
        long long v = p[threadIdx.x];
        int bad = (v < 0 || v >= NN) ? 1 : 0;
        unsigned m = __ballot_sync(0xffffffffu, bad);
        if (threadIdx.x == 0) {
            is64s = (m == 0) ? 1 : 0;
            if (blockIdx.x == 0) g_is64 = is64s;
        }
    }
    __syncthreads();
    int i = blockIdx.x * blockDim.x + threadIdx.x;
    if (i < NROWS4) {
        float4 v = ((const float4*)x)[i];
        ((uint2*)g_t0)[i] = make_uint2(packh2(v.x, v.y), packh2(v.z, v.w));
    }
    if (i < EE) {
        int d = is64s ? (int)((const long long*)ei)[EE + i] : ((const int*)ei)[EE + i];
        atomicAdd(&g_cnt[d], 1);
    }
}

// ---------------- CSR build -----------------------------------------------------
__global__ void k_scan1() {
    __shared__ int s[1024];
    int tid = threadIdx.x;
    int gid = blockIdx.x * 1024 + tid;
    int v = (gid < NN) ? g_cnt[gid] : 0;
    s[tid] = v;
    __syncthreads();
    for (int off = 1; off < 1024; off <<= 1) {
        int t = (tid >= off) ? s[tid - off] : 0;
        __syncthreads();
        s[tid] += t;
        __syncthreads();
    }
    int incl = s[tid];
    if (gid < NN) g_tmp[gid] = incl - v;
    if (tid == 1023) g_bsum[blockIdx.x] = incl;
}
__global__ void k_scan3b() {
    __shared__ int base;
    int sbk = blockIdx.x >> 2;
    if (threadIdx.x < 32) {
        int a = 0;
        for (int i = threadIdx.x; i < sbk; i += 32) a += g_bsum[i];
#pragma unroll
        for (int o = 16; o > 0; o >>= 1) a += __shfl_xor_sync(0xffffffffu, a, o);
        if (threadIdx.x == 0) base = a;
    }
    __syncthreads();
    int i = blockIdx.x * 256 + threadIdx.x;
    if (i < NN) {
        int rp = g_tmp[i] + base;
        g_rowptr[i] = rp;
        g_wcur[i] = rp;
        int c = g_cnt[i];
        g_cnt[i] = 0;
        g_invdeg[i] = 1.0f / (float)(c > 1 ? c : 1);
        if (i == 0) g_rowptr[NN] = EE;
    }
}
__global__ void k_scatter(const void* __restrict__ ei) {
    int e = blockIdx.x * blockDim.x + threadIdx.x;
    if (e >= EE) return;
    int s, d;
    if (g_is64) {
        const long long* p = (const long long*)ei;
        s = (int)p[e]; d = (int)p[EE + e];
    } else {
        const int* p = (const int*)ei;
        s = p[e]; d = p[EE + e];
    }
    g_col[atomicAdd(&g_wcur[d], 1)] = s;
}

// ---------------- weight transpose to fp16 (all 3 layers) ----------------------
__global__ void k_wsplit_all(const float* __restrict__ Wl0, const float* __restrict__ Wr0,
                             const float* __restrict__ Wl1, const float* __restrict__ Wr1,
                             const float* __restrict__ Wl2, const float* __restrict__ Wr2) {
    int idx = blockIdx.x * blockDim.x + threadIdx.x;
    if (idx >= 3 * 128 * 256) return;
    int l = idx >> 15;
    int r = idx & 32767;
    int k = r & 255, n = r >> 8;
    const float* Wl = (l == 0) ? Wl0 : ((l == 1) ? Wl1 : Wl2);
    const float* Wr = (l == 0) ? Wr0 : ((l == 1) ? Wr1 : Wr2);
    float w = (k < 128) ? Wl[k * 128 + n] : Wr[(k - 128) * 128 + n];
    g_wt[l][n * 256 + k] = __float2half_rn(w);
}

// ---------------- FUSED: gather-mean + HMMA GEMM + bias + LN + act -------------
// smem: AG0 (agg dims 0-63) 16KB | AG1 (agg dims 64-127) 16KB | X tile 16KB | W tile 16KB
#define AG0_T 0
#define AG1_T 16384
#define XS_T  32768
#define WS_T  49152
#define SM_TOTAL 65536

__global__ __launch_bounds__(256, 2)
void k_fused(const __half* __restrict__ X, const __half* __restrict__ W,
             const float* __restrict__ bl, const float* __restrict__ gg,
             const float* __restrict__ bb,
             float* __restrict__ outf, __half* __restrict__ outh, int mode)
{
    extern __shared__ char smem[];
    uint32_t sb = smem_u32(smem);
    int tid = threadIdx.x;
    int wid = tid >> 5;
    int lane = tid & 31;
    int row0 = blockIdx.x * 128;
    int m0 = (wid & 3) * 32;
    int n0 = (wid >> 2) * 64;
    int t = lane & 3, g = lane >> 2;

    // ================= gather phase: mean of neighbors -> AG tiles ============
    {
        uint32_t agbase = (lane < 16) ? AG0_T : AG1_T;
        uint32_t cb = (uint32_t)((lane & 15) * 8);
        for (int i = 0; i < 16; i++) {
            int lr = wid * 16 + i;
            int r = row0 + lr;
            float a0 = 0.f, a1 = 0.f, a2 = 0.f, a3 = 0.f;
            if (r < NN) {
                int beg = g_rowptr[r], end = g_rowptr[r + 1];
                int j = beg;
                for (; j + 3 < end; j += 4) {
                    int s0 = __ldg(&g_col[j]), s1 = __ldg(&g_col[j + 1]);
                    int s2 = __ldg(&g_col[j + 2]), s3 = __ldg(&g_col[j + 3]);
                    uint2 v0 = *(const uint2*)(X + (size_t)s0 * DD + lane * 4);
                    uint2 v1 = *(const uint2*)(X + (size_t)s1 * DD + lane * 4);
                    uint2 v2 = *(const uint2*)(X + (size_t)s2 * DD + lane * 4);
                    uint2 v3 = *(const uint2*)(X + (size_t)s3 * DD + lane * 4);
                    float2 p;
                    p = __half22float2(*(__half2*)&v0.x); a0 += p.x; a1 += p.y;
                    p = __half22float2(*(__half2*)&v0.y); a2 += p.x; a3 += p.y;
                    p = __half22float2(*(__half2*)&v1.x); a0 += p.x; a1 += p.y;
                    p = __half22float2(*(__half2*)&v1.y); a2 += p.x; a3 += p.y;
                    p = __half22float2(*(__half2*)&v2.x); a0 += p.x; a1 += p.y;
                    p = __half22float2(*(__half2*)&v2.y); a2 += p.x; a3 += p.y;
                    p = __half22float2(*(__half2*)&v3.x); a0 += p.x; a1 += p.y;
                    p = __half22float2(*(__half2*)&v3.y); a2 += p.x; a3 += p.y;
                }
                for (; j < end; j++) {
                    int s0 = __ldg(&g_col[j]);
                    uint2 v0 = *(const uint2*)(X + (size_t)s0 * DD + lane * 4);
                    float2 p;
                    p = __half22float2(*(__half2*)&v0.x); a0 += p.x; a1 += p.y;
                    p = __half22float2(*(__half2*)&v0.y); a2 += p.x; a3 += p.y;
                }
                float id = g_invdeg[r];
                a0 *= id; a1 *= id; a2 *= id; a3 *= id;
            }
            uint32_t smr = (uint32_t)(lr & 7) << 4;
            *(uint2*)(smem + agbase + (uint32_t)lr * 128u + (cb ^ smr)) =
                make_uint2(packh2(a0, a1), packh2(a2, a3));
        }
    }

    // ================= MMA phase ==============================================
    float acc[2][8][4];
#pragma unroll
    for (int mi = 0; mi < 2; mi++)
#pragma unroll
        for (int ni = 0; ni < 8; ni++)
#pragma unroll
            for (int q = 0; q < 4; q++) acc[mi][ni][q] = 0.f;

    uint32_t swzm = (uint32_t)(lane & 7) << 4;
    uint32_t a_row = m0 + (lane & 7) + ((lane >> 3) & 1) * 8;
    uint32_t a_kb = ((lane >> 4) & 1) * 16;
    uint32_t aoff[2] = { a_row * 128u, (a_row + 16u) * 128u };
    uint32_t jj = lane >> 3;
    uint32_t b_kb = (jj & 1) * 16;
    uint32_t b_row = n0 + (jj >> 1) * 8 + (lane & 7);
    uint32_t boff[4];
#pragma unroll
    for (int p = 0; p < 4; p++) boff[p] = (b_row + p * 16u) * 128u;

    int srow = tid >> 1, half = tid & 1;
    uint32_t sm = (uint32_t)(srow & 7) << 4;
    int grow = row0 + srow;
    int rok = grow < NN;
    int grc = rok ? grow : 0;
    uint32_t rb = (uint32_t)srow * 128u;

    __syncthreads();   // AG tiles complete

    for (int c = 0; c < 4; c++) {
        if (c) __syncthreads();
        {
            const __half* pw = W + srow * 256 + c * 64 + half * 32;
#pragma unroll
            for (int q = 0; q < 4; q++) {
                uint32_t off = rb + (((uint32_t)(half * 64 + q * 16)) ^ sm);
                cp_async16z(sb + WS_T + off, pw + q * 8, 1);
            }
            if (c >= 2) {
                const __half* pa = X + (size_t)grc * 128 + (c & 1) * 64 + half * 32;
#pragma unroll
                for (int q = 0; q < 4; q++) {
                    uint32_t off = rb + (((uint32_t)(half * 64 + q * 16)) ^ sm);
                    cp_async16z(sb + XS_T + off, pa + q * 8, rok);
                }
            }
            asm volatile("cp.async.commit_group;" ::: "memory");
            asm volatile("cp.async.wait_group 0;" ::: "memory");
        }
        __syncthreads();

        uint32_t abase = (c == 0) ? AG0_T : ((c == 1) ? AG1_T : XS_T);
#pragma unroll
        for (int ks = 0; ks < 4; ks++) {
            uint32_t kxa = ((uint32_t)(ks * 32) + a_kb) ^ swzm;
            uint32_t kxb = ((uint32_t)(ks * 32) + b_kb) ^ swzm;
            uint32_t ar[2][4], br[4][4];
#pragma unroll
            for (int mi = 0; mi < 2; mi++)
                ldm_x4(ar[mi], sb + abase + aoff[mi] + kxa);
#pragma unroll
            for (int p = 0; p < 4; p++)
                ldm_x4(br[p], sb + WS_T + boff[p] + kxb);
#pragma unroll
            for (int mi = 0; mi < 2; mi++) {
#pragma unroll
                for (int p = 0; p < 4; p++) {
                    mma16816(acc[mi][2 * p],     ar[mi], br[p][0], br[p][1]);
                    mma16816(acc[mi][2 * p + 1], ar[mi], br[p][2], br[p][3]);
                }
            }
        }
    }
    __syncthreads();   // tiles dead; smem reused for reductions

    // ---- epilogue: bias + LN (+ELU / L2-normalize) ----
    const float2* bl2 = (const float2*)bl;
    const float2* g2 = (const float2*)gg;
    const float2* b2 = (const float2*)bb;
    float2 blv[8], gv[8], bv[8];
#pragma unroll
    for (int ni = 0; ni < 8; ni++) {
        int cp = n0 / 2 + ni * 4 + t;
        blv[ni] = __ldg(&bl2[cp]);
        gv[ni] = __ldg(&g2[cp]);
        bv[ni] = __ldg(&b2[cp]);
    }
    float s1[4] = {0, 0, 0, 0}, s2[4] = {0, 0, 0, 0};
#pragma unroll
    for (int mi = 0; mi < 2; mi++)
#pragma unroll
        for (int ni = 0; ni < 8; ni++) {
            float a0 = acc[mi][ni][0] + blv[ni].x;
            float a1 = acc[mi][ni][1] + blv[ni].y;
            float a2 = acc[mi][ni][2] + blv[ni].x;
            float a3 = acc[mi][ni][3] + blv[ni].y;
            acc[mi][ni][0] = a0; acc[mi][ni][1] = a1;
            acc[mi][ni][2] = a2; acc[mi][ni][3] = a3;
            s1[2 * mi] += a0 + a1;       s2[2 * mi] += a0 * a0 + a1 * a1;
            s1[2 * mi + 1] += a2 + a3;   s2[2 * mi + 1] += a2 * a2 + a3 * a3;
        }
#pragma unroll
    for (int q = 0; q < 4; q++) {
        s1[q] += __shfl_xor_sync(0xffffffffu, s1[q], 1);
        s1[q] += __shfl_xor_sync(0xffffffffu, s1[q], 2);
        s2[q] += __shfl_xor_sync(0xffffffffu, s2[q], 1);
        s2[q] += __shfl_xor_sync(0xffffffffu, s2[q], 2);
    }
    float2* red = (float2*)smem;
    float* red2 = (float*)(smem + 2048);
    int hh = wid >> 2;
    int R[4] = { m0 + g, m0 + 8 + g, m0 + 16 + g, m0 + 24 + g };
    if (t == 0) {
#pragma unroll
        for (int q = 0; q < 4; q++) red[hh * 128 + R[q]] = make_float2(s1[q], s2[q]);
    }
    __syncthreads();
    float mu[4], rs[4];
#pragma unroll
    for (int q = 0; q < 4; q++) {
        float2 o = red[(1 - hh) * 128 + R[q]];
        float t1 = s1[q] + o.x, t2 = s2[q] + o.y;
        float m = t1 * (1.0f / 128.0f);
        float var = t2 * (1.0f / 128.0f) - m * m;
        mu[q] = m;
        rs[q] = rsqrtf(var + 1e-5f);
    }
    float qs[4] = {0, 0, 0, 0};
#pragma unroll
    for (int mi = 0; mi < 2; mi++)
#pragma unroll
        for (int ni = 0; ni < 8; ni++) {
            float y0 = (acc[mi][ni][0] - mu[2 * mi]) * rs[2 * mi] * gv[ni].x + bv[ni].x;
            float y1 = (acc[mi][ni][1] - mu[2 * mi]) * rs[2 * mi] * gv[ni].y + bv[ni].y;
            float y2 = (acc[mi][ni][2] - mu[2 * mi + 1]) * rs[2 * mi + 1] * gv[ni].x + bv[ni].x;
            float y3 = (acc[mi][ni][3] - mu[2 * mi + 1]) * rs[2 * mi + 1] * gv[ni].y + bv[ni].y;
            if (mode == 0) {
                y0 = (y0 > 0.f) ? y0 : expm1f(y0);
                y1 = (y1 > 0.f) ? y1 : expm1f(y1);
                y2 = (y2 > 0.f) ? y2 : expm1f(y2);
                y3 = (y3 > 0.f) ? y3 : expm1f(y3);
            } else {
                qs[2 * mi] += y0 * y0 + y1 * y1;
                qs[2 * mi + 1] += y2 * y2 + y3 * y3;
            }
            acc[mi][ni][0] = y0; acc[mi][ni][1] = y1;
            acc[mi][ni][2] = y2; acc[mi][ni][3] = y3;
        }
    float sc[4] = {1.f, 1.f, 1.f, 1.f};
    if (mode == 1) {
#pragma unroll
        for (int q = 0; q < 4; q++) {
            qs[q] += __shfl_xor_sync(0xffffffffu, qs[q], 1);
            qs[q] += __shfl_xor_sync(0xffffffffu, qs[q], 2);
        }
        if (t == 0) {
#pragma unroll
            for (int q = 0; q < 4; q++) red2[hh * 128 + R[q]] = qs[q];
        }
        __syncthreads();
#pragma unroll
        for (int q = 0; q < 4; q++) {
            float tot = qs[q] + red2[(1 - hh) * 128 + R[q]];
            sc[q] = 1.0f / fmaxf(sqrtf(tot), 1e-12f);
        }
    }
#pragma unroll
    for (int mi = 0; mi < 2; mi++) {
        int rA = row0 + R[2 * mi];
        int rB = row0 + R[2 * mi + 1];
#pragma unroll
        for (int ni = 0; ni < 8; ni++) {
            int col = n0 + ni * 8 + t * 2;
            float y0 = acc[mi][ni][0] * sc[2 * mi];
            float y1 = acc[mi][ni][1] * sc[2 * mi];
            float y2 = acc[mi][ni][2] * sc[2 * mi + 1];
            float y3 = acc[mi][ni][3] * sc[2 * mi + 1];
            if (mode == 0) {
                if (rA < NN)
                    *(uint32_t*)(outh + (size_t)rA * 128 + col) = packh2(y0, y1);
                if (rB < NN)
                    *(uint32_t*)(outh + (size_t)rB * 128 + col) = packh2(y2, y3);
            } else {
                if (rA < NN)
                    *(float2*)(outf + (size_t)rA * 128 + col) = make_float2(y0, y1);
                if (rB < NN)
                    *(float2*)(outf + (size_t)rB * 128 + col) = make_float2(y2, y3);
            }
        }
    }
}

// ---------------- launch --------------------------------------------------------
extern "C" void kernel_launch(void* const* d_in, const int* in_sizes, int n_in,
                              void* d_out, int out_size) {
    const float* x = (const float*)d_in[0];
    const void* ei = d_in[1];

    __half *t0, *t1, *wt;
    cudaGetSymbolAddress((void**)&t0, g_t0);
    cudaGetSymbolAddress((void**)&t1, g_t1);
    cudaGetSymbolAddress((void**)&wt, g_wt);

    cudaFuncSetAttribute(k_fused, cudaFuncAttributeMaxDynamicSharedMemorySize, SM_TOTAL);

    const int TB = 256;
    const int EBLK = (EE + TB - 1) / TB;
    const int SCAN_NB = (NN + 1023) / 1024;
    const int NBLK = (NN + TB - 1) / TB;
    const int GEMM_BLK = (NN + 127) / 128;
    const int IH_BLK = (NROWS4 + TB - 1) / TB;

    const float* Wl0 = (const float*)d_in[2], *bl0 = (const float*)d_in[3];
    const float* Wr0 = (const float*)d_in[4], *g0 = (const float*)d_in[5], *b0 = (const float*)d_in[6];
    const float* Wl1 = (const float*)d_in[7], *bl1 = (const float*)d_in[8];
    const float* Wr1 = (const float*)d_in[9], *g1 = (const float*)d_in[10], *b1 = (const float*)d_in[11];
    const float* Wl2 = (const float*)d_in[12], *bl2 = (const float*)d_in[13];
    const float* Wr2 = (const float*)d_in[14], *g2 = (const float*)d_in[15], *b2 = (const float*)d_in[16];

    k_inithist<<<IH_BLK, TB>>>(x, ei);
    k_scan1<<<SCAN_NB, 1024>>>();
    k_scan3b<<<NBLK, TB>>>();
    k_scatter<<<EBLK, TB>>>(ei);
    k_wsplit_all<<<384, TB>>>(Wl0, Wr0, Wl1, Wr1, Wl2, Wr2);

    // fused gather+GEMM per layer
    k_fused<<<GEMM_BLK, TB, SM_TOTAL>>>(t0, wt,         bl0, g0, b0, nullptr, t1, 0);
    k_fused<<<GEMM_BLK, TB, SM_TOTAL>>>(t1, wt + 32768, bl1, g1, b1, nullptr, t0, 0);
    k_fused<<<GEMM_BLK, TB, SM_TOTAL>>>(t0, wt + 65536, bl2, g2, b2, (float*)d_out, nullptr, 1);
}

// round 10
// speedup vs baseline: 1.3053x; 1.3053x over previous
#include <cuda_runtime.h>
#include <cuda_fp16.h>
#include <math.h>
#include <cstdint>

#define NN 100000
#define EE 1600000
#define DD 128
#define NROWS4 ((NN * DD) / 4)

// ---------------- scratch (static device globals; no allocation) -------------
__device__ __align__(16) __half g_t0[NN * DD];     // activation ping (starts as x)
__device__ __align__(16) __half g_t1[NN * DD];     // activation pong
__device__ __align__(16) __half g_agg16[NN * DD];  // mean aggregate

__device__ int   g_col[EE];
__device__ int   g_cnt[NN];          // zero-initialized; re-zeroed by k_scan3b
__device__ int   g_rowptr[NN + 1];
__device__ int   g_wcur[NN];
__device__ float g_invdeg[NN];
__device__ int   g_tmp[NN];
__device__ int   g_bsum[128];
__device__ int   g_is64;

// transposed fp16 weights per layer: [n=128][k=256]
__device__ __align__(16) __half g_wt[3][128 * 256];

// ================= helpers =====================================================
__device__ __forceinline__ uint32_t smem_u32(const void* p) {
    uint32_t a;
    asm("{ .reg .u64 t; cvta.to.shared.u64 t, %1; cvt.u32.u64 %0, t; }" : "=r"(a) : "l"(p));
    return a;
}
__device__ __forceinline__ void ldm_x4(uint32_t* r, uint32_t addr) {
    asm volatile("ldmatrix.sync.aligned.m8n8.x4.shared.b16 {%0,%1,%2,%3}, [%4];"
                 : "=r"(r[0]), "=r"(r[1]), "=r"(r[2]), "=r"(r[3]) : "r"(addr));
}
__device__ __forceinline__ void mma16816(float* c, const uint32_t* a, uint32_t b0, uint32_t b1) {
    asm volatile(
        "mma.sync.aligned.m16n8k16.row.col.f32.f16.f16.f32 "
        "{%0,%1,%2,%3},{%4,%5,%6,%7},{%8,%9},{%0,%1,%2,%3};"
        : "+f"(c[0]), "+f"(c[1]), "+f"(c[2]), "+f"(c[3])
        : "r"(a[0]), "r"(a[1]), "r"(a[2]), "r"(a[3]), "r"(b0), "r"(b1));
}
__device__ __forceinline__ void cp_async16z(uint32_t dst, const void* src, int ok) {
    asm volatile("cp.async.cg.shared.global [%0], [%1], 16, %2;"
                 :: "r"(dst), "l"(src), "r"(ok ? 16 : 0) : "memory");
}
__device__ __forceinline__ uint32_t packh2(float a, float b) {
    __half2 h = __floats2half2_rn(a, b);
    return *(uint32_t*)&h;
}

// ---------------- fused init: x -> fp16 convert + degree histogram -------------
__global__ void k_inithist(const float* __restrict__ x, const void* __restrict__ ei) {
    __shared__ int is64s;
    if (threadIdx.x < 32) {
        const long long* p = (const long long*)ei;
        long long v = p[threadIdx.x];
        int bad = (v < 0 || v >= NN) ? 1 : 0;
        unsigned m = __ballot_sync(0xffffffffu, bad);
        if (threadIdx.x == 0) {
            is64s = (m == 0) ? 1 : 0;
            if (blockIdx.x == 0) g_is64 = is64s;
        }
    }
    __syncthreads();
    int i = blockIdx.x * blockDim.x + threadIdx.x;
    if (i < NROWS4) {
        float4 v = ((const float4*)x)[i];
        ((uint2*)g_t0)[i] = make_uint2(packh2(v.x, v.y), packh2(v.z, v.w));
    }
    if (i < EE) {
        int d = is64s ? (int)((const long long*)ei)[EE + i] : ((const int*)ei)[EE + i];
        atomicAdd(&g_cnt[d], 1);
    }
}

// ---------------- CSR build -----------------------------------------------------
__global__ void k_scan1() {
    __shared__ int s[1024];
    int tid = threadIdx.x;
    int gid = blockIdx.x * 1024 + tid;
    int v = (gid < NN) ? g_cnt[gid] : 0;
    s[tid] = v;
    __syncthreads();
    for (int off = 1; off < 1024; off <<= 1) {
        int t = (tid >= off) ? s[tid - off] : 0;
        __syncthreads();
        s[tid] += t;
        __syncthreads();
    }
    int incl = s[tid];
    if (gid < NN) g_tmp[gid] = incl - v;
    if (tid == 1023) g_bsum[blockIdx.x] = incl;
}
__global__ void k_scan3b() {
    __shared__ int base;
    int sbk = blockIdx.x >> 2;
    if (threadIdx.x < 32) {
        int a = 0;
        for (int i = threadIdx.x; i < sbk; i += 32) a += g_bsum[i];
#pragma unroll
        for (int o = 16; o > 0; o >>= 1) a += __shfl_xor_sync(0xffffffffu, a, o);
        if (threadIdx.x == 0) base = a;
    }
    __syncthreads();
    int i = blockIdx.x * 256 + threadIdx.x;
    if (i < NN) {
        int rp = g_tmp[i] + base;
        g_rowptr[i] = rp;
        g_wcur[i] = rp;
        int c = g_cnt[i];
        g_cnt[i] = 0;
        g_invdeg[i] = 1.0f / (float)(c > 1 ? c : 1);
        if (i == 0) g_rowptr[NN] = EE;
    }
}
__global__ void k_scatter(const void* __restrict__ ei) {
    int e = blockIdx.x * blockDim.x + threadIdx.x;
    if (e >= EE) return;
    int s, d;
    if (g_is64) {
        const long long* p = (const long long*)ei;
        s = (int)p[e]; d = (int)p[EE + e];
    } else {
        const int* p = (const int*)ei;
        s = p[e]; d = p[EE + e];
    }
    g_col[atomicAdd(&g_wcur[d], 1)] = s;
}

// ---------------- mean aggregation: warp per node, half-warp per neighbor ------
// lanes 0-15: even neighbors, lanes 16-31: odd neighbors; each lane covers 8 dims
__global__ void k_aggregate(const __half* __restrict__ tb) {
    int warp = (blockIdx.x * blockDim.x + threadIdx.x) >> 5;
    int lane = threadIdx.x & 31;
    if (warp >= NN) return;
    int hl = lane >> 4;          // which half-warp
    int ln = lane & 15;          // dim group: covers dims ln*8 .. ln*8+7
    int beg = g_rowptr[warp];
    int end = g_rowptr[warp + 1];

    float ac[8];
#pragma unroll
    for (int q = 0; q < 8; q++) ac[q] = 0.f;

    const __half* base = tb + (size_t)ln * 8;
    int j = beg + hl;
    // 4 neighbors in flight per lane (16B each)
    for (; j + 6 < end; j += 8) {
        int s0 = __ldg(&g_col[j]);
        int s1 = __ldg(&g_col[j + 2]);
        int s2 = __ldg(&g_col[j + 4]);
        int s3 = __ldg(&g_col[j + 6]);
        uint4 v0 = *(const uint4*)(base + (size_t)s0 * DD);
        uint4 v1 = *(const uint4*)(base + (size_t)s1 * DD);
        uint4 v2 = *(const uint4*)(base + (size_t)s2 * DD);
        uint4 v3 = *(const uint4*)(base + (size_t)s3 * DD);
        float2 p;
#define ACC8(v) \
        p = __half22float2(*(__half2*)&(v).x); ac[0] += p.x; ac[1] += p.y; \
        p = __half22float2(*(__half2*)&(v).y); ac[2] += p.x; ac[3] += p.y; \
        p = __half22float2(*(__half2*)&(v).z); ac[4] += p.x; ac[5] += p.y; \
        p = __half22float2(*(__half2*)&(v).w); ac[6] += p.x; ac[7] += p.y;
        ACC8(v0) ACC8(v1) ACC8(v2) ACC8(v3)
    }
    for (; j < end; j += 2) {
        int s0 = __ldg(&g_col[j]);
        uint4 v0 = *(const uint4*)(base + (size_t)s0 * DD);
        float2 p;
        ACC8(v0)
    }
#undef ACC8
    // combine the two halves
#pragma unroll
    for (int q = 0; q < 8; q++)
        ac[q] += __shfl_xor_sync(0xffffffffu, ac[q], 16);

    if (hl == 0) {
        float id = g_invdeg[warp];
        uint4 o = make_uint4(packh2(ac[0] * id, ac[1] * id), packh2(ac[2] * id, ac[3] * id),
                             packh2(ac[4] * id, ac[5] * id), packh2(ac[6] * id, ac[7] * id));
        *(uint4*)(g_agg16 + (size_t)warp * DD + ln * 8) = o;
    }
}

// ---------------- weight transpose to fp16 (all 3 layers) ----------------------
__global__ void k_wsplit_all(const float* __restrict__ Wl0, const float* __restrict__ Wr0,
                             const float* __restrict__ Wl1, const float* __restrict__ Wr1,
                             const float* __restrict__ Wl2, const float* __restrict__ Wr2) {
    int idx = blockIdx.x * blockDim.x + threadIdx.x;
    if (idx >= 3 * 128 * 256) return;
    int l = idx >> 15;
    int r = idx & 32767;
    int k = r & 255, n = r >> 8;
    const float* Wl = (l == 0) ? Wl0 : ((l == 1) ? Wl1 : Wl2);
    const float* Wr = (l == 0) ? Wr0 : ((l == 1) ? Wr1 : Wr2);
    float w = (k < 128) ? Wl[k * 128 + n] : Wr[(k - 128) * 128 + n];
    g_wt[l][n * 256 + k] = __float2half_rn(w);
}

// ---------------- HMMA GEMM + bias + LayerNorm + ELU / L2-norm -----------------
// 32KB smem: A fp16 (16KB) + W fp16 (16KB), both 128x64, 128B rows, swizzled
#define AS_T  0
#define WS_T  16384
#define SM_TOTAL 32768

__global__ __launch_bounds__(256, 2)
void k_gemm_mma(const __half* __restrict__ Agg, const __half* __restrict__ X,
                const __half* __restrict__ W,
                const float* __restrict__ bl, const float* __restrict__ gg,
                const float* __restrict__ bb,
                float* __restrict__ outf, __half* __restrict__ outh, int mode)
{
    extern __shared__ char smem[];
    uint32_t sb = smem_u32(smem);
    int tid = threadIdx.x;
    int wid = tid >> 5;
    int lane = tid & 31;
    int row0 = blockIdx.x * 128;
    int m0 = (wid & 3) * 32;
    int n0 = (wid >> 2) * 64;
    int t = lane & 3, g = lane >> 2;

    float acc[2][8][4];
#pragma unroll
    for (int mi = 0; mi < 2; mi++)
#pragma unroll
        for (int ni = 0; ni < 8; ni++)
#pragma unroll
            for (int q = 0; q < 4; q++) acc[mi][ni][q] = 0.f;

    uint32_t swzm = (uint32_t)(lane & 7) << 4;
    uint32_t a_row = m0 + (lane & 7) + ((lane >> 3) & 1) * 8;
    uint32_t a_kb = ((lane >> 4) & 1) * 16;
    uint32_t aoff[2] = { a_row * 128u, (a_row + 16u) * 128u };
    uint32_t jj = lane >> 3;
    uint32_t b_kb = (jj & 1) * 16;
    uint32_t b_row = n0 + (jj >> 1) * 8 + (lane & 7);
    uint32_t boff[4];
#pragma unroll
    for (int p = 0; p < 4; p++) boff[p] = (b_row + p * 16u) * 128u;

    int srow = tid >> 1, half = tid & 1;
    uint32_t sm = (uint32_t)(srow & 7) << 4;
    int grow = row0 + srow;
    int rok = grow < NN;
    int grc = rok ? grow : 0;
    uint32_t rb = (uint32_t)srow * 128u;

    for (int c = 0; c < 4; c++) {
        if (c) __syncthreads();
        {
            const __half* pa = ((c < 2) ? Agg : X) + (size_t)grc * 128 + (c & 1) * 64 + half * 32;
            const __half* pw = W + srow * 256 + c * 64 + half * 32;
#pragma unroll
            for (int q = 0; q < 4; q++) {
                uint32_t off = rb + (((uint32_t)(half * 64 + q * 16)) ^ sm);
                cp_async16z(sb + AS_T + off, pa + q * 8, rok);
                cp_async16z(sb + WS_T + off, pw + q * 8, 1);
            }
            asm volatile("cp.async.commit_group;" ::: "memory");
            asm volatile("cp.async.wait_group 0;" ::: "memory");
        }
        __syncthreads();

#pragma unroll
        for (int ks = 0; ks < 4; ks++) {
            uint32_t kxa = ((uint32_t)(ks * 32) + a_kb) ^ swzm;
            uint32_t kxb = ((uint32_t)(ks * 32) + b_kb) ^ swzm;
            uint32_t ar[2][4], br[4][4];
#pragma unroll
            for (int mi = 0; mi < 2; mi++)
                ldm_x4(ar[mi], sb + AS_T + aoff[mi] + kxa);
#pragma unroll
            for (int p = 0; p < 4; p++)
                ldm_x4(br[p], sb + WS_T + boff[p] + kxb);
#pragma unroll
            for (int mi = 0; mi < 2; mi++) {
#pragma unroll
                for (int p = 0; p < 4; p++) {
                    mma16816(acc[mi][2 * p],     ar[mi], br[p][0], br[p][1]);
                    mma16816(acc[mi][2 * p + 1], ar[mi], br[p][2], br[p][3]);
                }
            }
        }
    }
    __syncthreads();

    // ---- epilogue: bias + LN (+ELU / L2-normalize) ----
    const float2* bl2 = (const float2*)bl;
    const float2* g2 = (const float2*)gg;
    const float2* b2 = (const float2*)bb;
    float2 blv[8], gv[8], bv[8];
#pragma unroll
    for (int ni = 0; ni < 8; ni++) {
        int cp = n0 / 2 + ni * 4 + t;
        blv[ni] = __ldg(&bl2[cp]);
        gv[ni] = __ldg(&g2[cp]);
        bv[ni] = __ldg(&b2[cp]);
    }
    float s1[4] = {0, 0, 0, 0}, s2[4] = {0, 0, 0, 0};
#pragma unroll
    for (int mi = 0; mi < 2; mi++)
#pragma unroll
        for (int ni = 0; ni < 8; ni++) {
            float a0 = acc[mi][ni][0] + blv[ni].x;
            float a1 = acc[mi][ni][1] + blv[ni].y;
            float a2 = acc[mi][ni][2] + blv[ni].x;
            float a3 = acc[mi][ni][3] + blv[ni].y;
            acc[mi][ni][0] = a0; acc[mi][ni][1] = a1;
            acc[mi][ni][2] = a2; acc[mi][ni][3] = a3;
            s1[2 * mi] += a0 + a1;       s2[2 * mi] += a0 * a0 + a1 * a1;
            s1[2 * mi + 1] += a2 + a3;   s2[2 * mi + 1] += a2 * a2 + a3 * a3;
        }
#pragma unroll
    for (int q = 0; q < 4; q++) {
        s1[q] += __shfl_xor_sync(0xffffffffu, s1[q], 1);
        s1[q] += __shfl_xor_sync(0xffffffffu, s1[q], 2);
        s2[q] += __shfl_xor_sync(0xffffffffu, s2[q], 1);
        s2[q] += __shfl_xor_sync(0xffffffffu, s2[q], 2);
    }
    float2* red = (float2*)smem;
    float* red2 = (float*)(smem + 2048);
    int hh = wid >> 2;
    int R[4] = { m0 + g, m0 + 8 + g, m0 + 16 + g, m0 + 24 + g };
    if (t == 0) {
#pragma unroll
        for (int q = 0; q < 4; q++) red[hh * 128 + R[q]] = make_float2(s1[q], s2[q]);
    }
    __syncthreads();
    float mu[4], rs[4];
#pragma unroll
    for (int q = 0; q < 4; q++) {
        float2 o = red[(1 - hh) * 128 + R[q]];
        float t1 = s1[q] + o.x, t2 = s2[q] + o.y;
        float m = t1 * (1.0f / 128.0f);
        float var = t2 * (1.0f / 128.0f) - m * m;
        mu[q] = m;
        rs[q] = rsqrtf(var + 1e-5f);
    }
    float qs[4] = {0, 0, 0, 0};
#pragma unroll
    for (int mi = 0; mi < 2; mi++)
#pragma unroll
        for (int ni = 0; ni < 8; ni++) {
            float y0 = (acc[mi][ni][0] - mu[2 * mi]) * rs[2 * mi] * gv[ni].x + bv[ni].x;
            float y1 = (acc[mi][ni][1] - mu[2 * mi]) * rs[2 * mi] * gv[ni].y + bv[ni].y;
            float y2 = (acc[mi][ni][2] - mu[2 * mi + 1]) * rs[2 * mi + 1] * gv[ni].x + bv[ni].x;
            float y3 = (acc[mi][ni][3] - mu[2 * mi + 1]) * rs[2 * mi + 1] * gv[ni].y + bv[ni].y;
            if (mode == 0) {
                y0 = (y0 > 0.f) ? y0 : expm1f(y0);
                y1 = (y1 > 0.f) ? y1 : expm1f(y1);
                y2 = (y2 > 0.f) ? y2 : expm1f(y2);
                y3 = (y3 > 0.f) ? y3 : expm1f(y3);
            } else {
                qs[2 * mi] += y0 * y0 + y1 * y1;
                qs[2 * mi + 1] += y2 * y2 + y3 * y3;
            }
            acc[mi][ni][0] = y0; acc[mi][ni][1] = y1;
            acc[mi][ni][2] = y2; acc[mi][ni][3] = y3;
        }
    float sc[4] = {1.f, 1.f, 1.f, 1.f};
    if (mode == 1) {
#pragma unroll
        for (int q = 0; q < 4; q++) {
            qs[q] += __shfl_xor_sync(0xffffffffu, qs[q], 1);
            qs[q] += __shfl_xor_sync(0xffffffffu, qs[q], 2);
        }
        if (t == 0) {
#pragma unroll
            for (int q = 0; q < 4; q++) red2[hh * 128 + R[q]] = qs[q];
        }
        __syncthreads();
#pragma unroll
        for (int q = 0; q < 4; q++) {
            float tot = qs[q] + red2[(1 - hh) * 128 + R[q]];
            sc[q] = 1.0f / fmaxf(sqrtf(tot), 1e-12f);
        }
    }
#pragma unroll
    for (int mi = 0; mi < 2; mi++) {
        int rA = row0 + R[2 * mi];
        int rB = row0 + R[2 * mi + 1];
#pragma unroll
        for (int ni = 0; ni < 8; ni++) {
            int col = n0 + ni * 8 + t * 2;
            float y0 = acc[mi][ni][0] * sc[2 * mi];
            float y1 = acc[mi][ni][1] * sc[2 * mi];
            float y2 = acc[mi][ni][2] * sc[2 * mi + 1];
            float y3 = acc[mi][ni][3] * sc[2 * mi + 1];
            if (mode == 0) {
                if (rA < NN)
                    *(uint32_t*)(outh + (size_t)rA * 128 + col) = packh2(y0, y1);
                if (rB < NN)
                    *(uint32_t*)(outh + (size_t)rB * 128 + col) = packh2(y2, y3);
            } else {
                if (rA < NN)
                    *(float2*)(outf + (size_t)rA * 128 + col) = make_float2(y0, y1);
                if (rB < NN)
                    *(float2*)(outf + (size_t)rB * 128 + col) = make_float2(y2, y3);
            }
        }
    }
}

// ---------------- launch --------------------------------------------------------
extern "C" void kernel_launch(void* const* d_in, const int* in_sizes, int n_in,
                              void* d_out, int out_size) {
    const float* x = (const float*)d_in[0];
    const void* ei = d_in[1];

    __half *t0, *t1, *agg16, *wt;
    cudaGetSymbolAddress((void**)&t0, g_t0);
    cudaGetSymbolAddress((void**)&t1, g_t1);
    cudaGetSymbolAddress((void**)&agg16, g_agg16);
    cudaGetSymbolAddress((void**)&wt, g_wt);

    cudaFuncSetAttribute(k_gemm_mma, cudaFuncAttributeMaxDynamicSharedMemorySize, SM_TOTAL);

    const int TB = 256;
    const int EBLK = (EE + TB - 1) / TB;
    const int SCAN_NB = (NN + 1023) / 1024;
    const int NBLK = (NN + TB - 1) / TB;
    const int AGG_BLK = (NN * 32 + TB - 1) / TB;
    const int GEMM_BLK = (NN + 127) / 128;
    const int IH_BLK = (NROWS4 + TB - 1) / TB;

    const float* Wl0 = (const float*)d_in[2], *bl0 = (const float*)d_in[3];
    const float* Wr0 = (const float*)d_in[4], *g0 = (const float*)d_in[5], *b0 = (const float*)d_in[6];
    const float* Wl1 = (const float*)d_in[7], *bl1 = (const float*)d_in[8];
    const float* Wr1 = (const float*)d_in[9], *g1 = (const float*)d_in[10], *b1 = (const float*)d_in[11];
    const float* Wl2 = (const float*)d_in[12], *bl2 = (const float*)d_in[13];
    const float* Wr2 = (const float*)d_in[14], *g2 = (const float*)d_in[15], *b2 = (const float*)d_in[16];

    k_inithist<<<IH_BLK, TB>>>(x, ei);
    k_scan1<<<SCAN_NB, 1024>>>();
    k_scan3b<<<NBLK, TB>>>();
    k_scatter<<<EBLK, TB>>>(ei);
    k_wsplit_all<<<384, TB>>>(Wl0, Wr0, Wl1, Wr1, Wl2, Wr2);

    // layer 0
    k_aggregate<<<AGG_BLK, TB>>>(t0);
    k_gemm_mma<<<GEMM_BLK, TB, SM_TOTAL>>>(agg16, t0, wt, bl0, g0, b0,
                                           nullptr, t1, 0);
    // layer 1
    k_aggregate<<<AGG_BLK, TB>>>(t1);
    k_gemm_mma<<<GEMM_BLK, TB, SM_TOTAL>>>(agg16, t1, wt + 32768, bl1, g1, b1,
                                           nullptr, t0, 0);
    // layer 2
    k_aggregate<<<AGG_BLK, TB>>>(t0);
    k_gemm_mma<<<GEMM_BLK, TB, SM_TOTAL>>>(agg16, t0, wt + 65536, bl2, g2, b2,
                                           (float*)d_out, nullptr, 1);
}

// round 11
// speedup vs baseline: 1.3586x; 1.0409x over previous
#include <cuda_runtime.h>
#include <cuda_fp16.h>
#include <math.h>
#include <cstdint>

#define NN 100000
#define EE 1600000
#define DD 128
#define NROWS4 ((NN * DD) / 4)

// ---------------- scratch (static device globals; no allocation) -------------
__device__ __align__(16) __half g_t0[NN * DD];     // activation ping (starts as x)
__device__ __align__(16) __half g_t1[NN * DD];     // activation pong
__device__ __align__(16) __half g_agg16[NN * DD];  // mean aggregate

__device__ int   g_col[EE];
__device__ int   g_cnt[NN];          // zero-initialized; re-zeroed by k_scan3b
__device__ int   g_rowptr[NN + 1];
__device__ int   g_wcur[NN];
__device__ float g_invdeg[NN];
__device__ int   g_tmp[NN];
__device__ int   g_bsum[128];
__device__ int   g_is64;

// transposed fp16 weights per layer: [n=128][k=256]
__device__ __align__(16) __half g_wt[3][128 * 256];

// ================= helpers =====================================================
__device__ __forceinline__ uint32_t smem_u32(const void* p) {
    uint32_t a;
    asm("{ .reg .u64 t; cvta.to.shared.u64 t, %1; cvt.u32.u64 %0, t; }" : "=r"(a) : "l"(p));
    return a;
}
__device__ __forceinline__ void ldm_x4(uint32_t* r, uint32_t addr) {
    asm volatile("ldmatrix.sync.aligned.m8n8.x4.shared.b16 {%0,%1,%2,%3}, [%4];"
                 : "=r"(r[0]), "=r"(r[1]), "=r"(r[2]), "=r"(r[3]) : "r"(addr));
}
__device__ __forceinline__ void mma16816(float* c, const uint32_t* a, uint32_t b0, uint32_t b1) {
    asm volatile(
        "mma.sync.aligned.m16n8k16.row.col.f32.f16.f16.f32 "
        "{%0,%1,%2,%3},{%4,%5,%6,%7},{%8,%9},{%0,%1,%2,%3};"
        : "+f"(c[0]), "+f"(c[1]), "+f"(c[2]), "+f"(c[3])
        : "r"(a[0]), "r"(a[1]), "r"(a[2]), "r"(a[3]), "r"(b0), "r"(b1));
}
__device__ __forceinline__ void cp_async16z(uint32_t dst, const void* src, int ok) {
    asm volatile("cp.async.cg.shared.global [%0], [%1], 16, %2;"
                 :: "r"(dst), "l"(src), "r"(ok ? 16 : 0) : "memory");
}
__device__ __forceinline__ uint32_t packh2(float a, float b) {
    __half2 h = __floats2half2_rn(a, b);
    return *(uint32_t*)&h;
}

// ---------------- fused init: x -> fp16 convert + degree histogram -------------
__global__ void k_inithist(const float* __restrict__ x, const void* __restrict__ ei) {
    __shared__ int is64s;
    if (threadIdx.x < 32) {
        const long long* p = (const long long*)ei;
        long long v = p[threadIdx.x];
        int bad = (v < 0 || v >= NN) ? 1 : 0;
        unsigned m = __ballot_sync(0xffffffffu, bad);
        if (threadIdx.x == 0) {
            is64s = (m == 0) ? 1 : 0;
            if (blockIdx.x == 0) g_is64 = is64s;
        }
    }
    __syncthreads();
    int i = blockIdx.x * blockDim.x + threadIdx.x;
    if (i < NROWS4) {
        float4 v = ((const float4*)x)[i];
        ((uint2*)g_t0)[i] = make_uint2(packh2(v.x, v.y), packh2(v.z, v.w));
    }
    if (i < EE) {
        int d = is64s ? (int)((const long long*)ei)[EE + i] : ((const int*)ei)[EE + i];
        atomicAdd(&g_cnt[d], 1);
    }
}

// ---------------- CSR build -----------------------------------------------------
__global__ void k_scan1() {
    __shared__ int s[1024];
    int tid = threadIdx.x;
    int gid = blockIdx.x * 1024 + tid;
    int v = (gid < NN) ? g_cnt[gid] : 0;
    s[tid] = v;
    __syncthreads();
    for (int off = 1; off < 1024; off <<= 1) {
        int t = (tid >= off) ? s[tid - off] : 0;
        __syncthreads();
        s[tid] += t;
        __syncthreads();
    }
    int incl = s[tid];
    if (gid < NN) g_tmp[gid] = incl - v;
    if (tid == 1023) g_bsum[blockIdx.x] = incl;
}
__global__ void k_scan3b() {
    __shared__ int base;
    int sbk = blockIdx.x >> 2;
    if (threadIdx.x < 32) {
        int a = 0;
        for (int i = threadIdx.x; i < sbk; i += 32) a += g_bsum[i];
#pragma unroll
        for (int o = 16; o > 0; o >>= 1) a += __shfl_xor_sync(0xffffffffu, a, o);
        if (threadIdx.x == 0) base = a;
    }
    __syncthreads();
    int i = blockIdx.x * 256 + threadIdx.x;
    if (i < NN) {
        int rp = g_tmp[i] + base;
        g_rowptr[i] = rp;
        g_wcur[i] = rp;
        int c = g_cnt[i];
        g_cnt[i] = 0;
        g_invdeg[i] = 1.0f / (float)(c > 1 ? c : 1);
        if (i == 0) g_rowptr[NN] = EE;
    }
}
__global__ void k_scatter(const void* __restrict__ ei) {
    int e = blockIdx.x * blockDim.x + threadIdx.x;
    if (e >= EE) return;
    int s, d;
    if (g_is64) {
        const long long* p = (const long long*)ei;
        s = (int)p[e]; d = (int)p[EE + e];
    } else {
        const int* p = (const int*)ei;
        s = p[e]; d = p[EE + e];
    }
    g_col[atomicAdd(&g_wcur[d], 1)] = s;
}

// ---------------- mean aggregation: warp per node, half-warp per neighbor ------
__global__ void k_aggregate(const __half* __restrict__ tb) {
    int warp = (blockIdx.x * blockDim.x + threadIdx.x) >> 5;
    int lane = threadIdx.x & 31;
    if (warp >= NN) return;
    int hl = lane >> 4;
    int ln = lane & 15;
    int beg = g_rowptr[warp];
    int end = g_rowptr[warp + 1];

    float ac[8];
#pragma unroll
    for (int q = 0; q < 8; q++) ac[q] = 0.f;

    const __half* base = tb + (size_t)ln * 8;
    int j = beg + hl;
    for (; j + 6 < end; j += 8) {
        int s0 = __ldg(&g_col[j]);
        int s1 = __ldg(&g_col[j + 2]);
        int s2 = __ldg(&g_col[j + 4]);
        int s3 = __ldg(&g_col[j + 6]);
        uint4 v0 = *(const uint4*)(base + (size_t)s0 * DD);
        uint4 v1 = *(const uint4*)(base + (size_t)s1 * DD);
        uint4 v2 = *(const uint4*)(base + (size_t)s2 * DD);
        uint4 v3 = *(const uint4*)(base + (size_t)s3 * DD);
        float2 p;
#define ACC8(v) \
        p = __half22float2(*(__half2*)&(v).x); ac[0] += p.x; ac[1] += p.y; \
        p = __half22float2(*(__half2*)&(v).y); ac[2] += p.x; ac[3] += p.y; \
        p = __half22float2(*(__half2*)&(v).z); ac[4] += p.x; ac[5] += p.y; \
        p = __half22float2(*(__half2*)&(v).w); ac[6] += p.x; ac[7] += p.y;
        ACC8(v0) ACC8(v1) ACC8(v2) ACC8(v3)
    }
    for (; j < end; j += 2) {
        int s0 = __ldg(&g_col[j]);
        uint4 v0 = *(const uint4*)(base + (size_t)s0 * DD);
        float2 p;
        ACC8(v0)
    }
#undef ACC8
#pragma unroll
    for (int q = 0; q < 8; q++)
        ac[q] += __shfl_xor_sync(0xffffffffu, ac[q], 16);

    if (hl == 0) {
        float id = g_invdeg[warp];
        uint4 o = make_uint4(packh2(ac[0] * id, ac[1] * id), packh2(ac[2] * id, ac[3] * id),
                             packh2(ac[4] * id, ac[5] * id), packh2(ac[6] * id, ac[7] * id));
        *(uint4*)(g_agg16 + (size_t)warp * DD + ln * 8) = o;
    }
}

// ---------------- weight transpose to fp16 (all 3 layers) ----------------------
__global__ void k_wsplit_all(const float* __restrict__ Wl0, const float* __restrict__ Wr0,
                             const float* __restrict__ Wl1, const float* __restrict__ Wr1,
                             const float* __restrict__ Wl2, const float* __restrict__ Wr2) {
    int idx = blockIdx.x * blockDim.x + threadIdx.x;
    if (idx >= 3 * 128 * 256) return;
    int l = idx >> 15;
    int r = idx & 32767;
    int k = r & 255, n = r >> 8;
    const float* Wl = (l == 0) ? Wl0 : ((l == 1) ? Wl1 : Wl2);
    const float* Wr = (l == 0) ? Wr0 : ((l == 1) ? Wr1 : Wr2);
    float w = (k < 128) ? Wl[k * 128 + n] : Wr[(k - 128) * 128 + n];
    g_wt[l][n * 256 + k] = __float2half_rn(w);
}

// ---------------- HMMA GEMM (double-buffered) + bias + LN + act ----------------
// 64KB smem: A0/A1/W0/W1 tiles, each 128x64 fp16 = 16KB, 128B rows, swizzled
#define AS0 0
#define AS1 16384
#define WS0 32768
#define WS1 49152
#define SM_TOTAL 65536

__global__ __launch_bounds__(256, 2)
void k_gemm_mma(const __half* __restrict__ Agg, const __half* __restrict__ X,
                const __half* __restrict__ W,
                const float* __restrict__ bl, const float* __restrict__ gg,
                const float* __restrict__ bb,
                float* __restrict__ outf, __half* __restrict__ outh, int mode)
{
    extern __shared__ char smem[];
    uint32_t sb = smem_u32(smem);
    int tid = threadIdx.x;
    int wid = tid >> 5;
    int lane = tid & 31;
    int row0 = blockIdx.x * 128;
    int m0 = (wid & 3) * 32;
    int n0 = (wid >> 2) * 64;
    int t = lane & 3, g = lane >> 2;

    float acc[2][8][4];
#pragma unroll
    for (int mi = 0; mi < 2; mi++)
#pragma unroll
        for (int ni = 0; ni < 8; ni++)
#pragma unroll
            for (int q = 0; q < 4; q++) acc[mi][ni][q] = 0.f;

    uint32_t swzm = (uint32_t)(lane & 7) << 4;
    uint32_t a_row = m0 + (lane & 7) + ((lane >> 3) & 1) * 8;
    uint32_t a_kb = ((lane >> 4) & 1) * 16;
    uint32_t aoff[2] = { a_row * 128u, (a_row + 16u) * 128u };
    uint32_t jj = lane >> 3;
    uint32_t b_kb = (jj & 1) * 16;
    uint32_t b_row = n0 + (jj >> 1) * 8 + (lane & 7);
    uint32_t boff[4];
#pragma unroll
    for (int p = 0; p < 4; p++) boff[p] = (b_row + p * 16u) * 128u;

    int srow = tid >> 1, half = tid & 1;
    uint32_t sm = (uint32_t)(srow & 7) << 4;
    int grow = row0 + srow;
    int rok = grow < NN;
    int grc = rok ? grow : 0;
    uint32_t rb = (uint32_t)srow * 128u;

    const uint32_t ABUF[2] = { AS0, AS1 };
    const uint32_t WBUF[2] = { WS0, WS1 };

    // issue chunk-c loads into buffer c&1
    auto issue = [&](int c) {
        uint32_t ab = ABUF[c & 1], wb = WBUF[c & 1];
        const __half* pa = ((c < 2) ? Agg : X) + (size_t)grc * 128 + (c & 1) * 64 + half * 32;
        const __half* pw = W + srow * 256 + c * 64 + half * 32;
#pragma unroll
        for (int q = 0; q < 4; q++) {
            uint32_t off = rb + (((uint32_t)(half * 64 + q * 16)) ^ sm);
            cp_async16z(sb + ab + off, pa + q * 8, rok);
            cp_async16z(sb + wb + off, pw + q * 8, 1);
        }
        asm volatile("cp.async.commit_group;" ::: "memory");
    };

    issue(0);
    for (int c = 0; c < 4; c++) {
        if (c < 3) issue(c + 1);
        if (c < 3) asm volatile("cp.async.wait_group 1;" ::: "memory");
        else       asm volatile("cp.async.wait_group 0;" ::: "memory");
        __syncthreads();

        uint32_t abase = sb + ABUF[c & 1];
        uint32_t wbase = sb + WBUF[c & 1];
#pragma unroll
        for (int ks = 0; ks < 4; ks++) {
            uint32_t kxa = ((uint32_t)(ks * 32) + a_kb) ^ swzm;
            uint32_t kxb = ((uint32_t)(ks * 32) + b_kb) ^ swzm;
            uint32_t ar[2][4], br[4][4];
#pragma unroll
            for (int mi = 0; mi < 2; mi++)
                ldm_x4(ar[mi], abase + aoff[mi] + kxa);
#pragma unroll
            for (int p = 0; p < 4; p++)
                ldm_x4(br[p], wbase + boff[p] + kxb);
#pragma unroll
            for (int mi = 0; mi < 2; mi++) {
#pragma unroll
                for (int p = 0; p < 4; p++) {
                    mma16816(acc[mi][2 * p],     ar[mi], br[p][0], br[p][1]);
                    mma16816(acc[mi][2 * p + 1], ar[mi], br[p][2], br[p][3]);
                }
            }
        }
        __syncthreads();   // buffer c&1 free for chunk c+2's issue next iteration
    }

    // ---- epilogue: bias + LN (+ELU / L2-normalize) ----
    const float2* bl2 = (const float2*)bl;
    const float2* g2 = (const float2*)gg;
    const float2* b2 = (const float2*)bb;
    float2 blv[8], gv[8], bv[8];
#pragma unroll
    for (int ni = 0; ni < 8; ni++) {
        int cp = n0 / 2 + ni * 4 + t;
        blv[ni] = __ldg(&bl2[cp]);
        gv[ni] = __ldg(&g2[cp]);
        bv[ni] = __ldg(&b2[cp]);
    }
    float s1[4] = {0, 0, 0, 0}, s2[4] = {0, 0, 0, 0};
#pragma unroll
    for (int mi = 0; mi < 2; mi++)
#pragma unroll
        for (int ni = 0; ni < 8; ni++) {
            float a0 = acc[mi][ni][0] + blv[ni].x;
            float a1 = acc[mi][ni][1] + blv[ni].y;
            float a2 = acc[mi][ni][2] + blv[ni].x;
            float a3 = acc[mi][ni][3] + blv[ni].y;
            acc[mi][ni][0] = a0; acc[mi][ni][1] = a1;
            acc[mi][ni][2] = a2; acc[mi][ni][3] = a3;
            s1[2 * mi] += a0 + a1;       s2[2 * mi] += a0 * a0 + a1 * a1;
            s1[2 * mi + 1] += a2 + a3;   s2[2 * mi + 1] += a2 * a2 + a3 * a3;
        }
#pragma unroll
    for (int q = 0; q < 4; q++) {
        s1[q] += __shfl_xor_sync(0xffffffffu, s1[q], 1);
        s1[q] += __shfl_xor_sync(0xffffffffu, s1[q], 2);
        s2[q] += __shfl_xor_sync(0xffffffffu, s2[q], 1);
        s2[q] += __shfl_xor_sync(0xffffffffu, s2[q], 2);
    }
    float2* red = (float2*)smem;
    float* red2 = (float*)(smem + 2048);
    int hh = wid >> 2;
    int R[4] = { m0 + g, m0 + 8 + g, m0 + 16 + g, m0 + 24 + g };
    if (t == 0) {
#pragma unroll
        for (int q = 0; q < 4; q++) red[hh * 128 + R[q]] = make_float2(s1[q], s2[q]);
    }
    __syncthreads();
    float mu[4], rs[4];
#pragma unroll
    for (int q = 0; q < 4; q++) {
        float2 o = red[(1 - hh) * 128 + R[q]];
        float t1 = s1[q] + o.x, t2 = s2[q] + o.y;
        float m = t1 * (1.0f / 128.0f);
        float var = t2 * (1.0f / 128.0f) - m * m;
        mu[q] = m;
        rs[q] = rsqrtf(var + 1e-5f);
    }
    float qs[4] = {0, 0, 0, 0};
#pragma unroll
    for (int mi = 0; mi < 2; mi++)
#pragma unroll
        for (int ni = 0; ni < 8; ni++) {
            float y0 = (acc[mi][ni][0] - mu[2 * mi]) * rs[2 * mi] * gv[ni].x + bv[ni].x;
            float y1 = (acc[mi][ni][1] - mu[2 * mi]) * rs[2 * mi] * gv[ni].y + bv[ni].y;
            float y2 = (acc[mi][ni][2] - mu[2 * mi + 1]) * rs[2 * mi + 1] * gv[ni].x + bv[ni].x;
            float y3 = (acc[mi][ni][3] - mu[2 * mi + 1]) * rs[2 * mi + 1] * gv[ni].y + bv[ni].y;
            if (mode == 0) {
                y0 = (y0 > 0.f) ? y0 : expm1f(y0);
                y1 = (y1 > 0.f) ? y1 : expm1f(y1);
                y2 = (y2 > 0.f) ? y2 : expm1f(y2);
                y3 = (y3 > 0.f) ? y3 : expm1f(y3);
            } else {
                qs[2 * mi] += y0 * y0 + y1 * y1;
                qs[2 * mi + 1] += y2 * y2 + y3 * y3;
            }
            acc[mi][ni][0] = y0; acc[mi][ni][1] = y1;
            acc[mi][ni][2] = y2; acc[mi][ni][3] = y3;
        }
    float sc[4] = {1.f, 1.f, 1.f, 1.f};
    if (mode == 1) {
#pragma unroll
        for (int q = 0; q < 4; q++) {
            qs[q] += __shfl_xor_sync(0xffffffffu, qs[q], 1);
            qs[q] += __shfl_xor_sync(0xffffffffu, qs[q], 2);
        }
        if (t == 0) {
#pragma unroll
            for (int q = 0; q < 4; q++) red2[hh * 128 + R[q]] = qs[q];
        }
        __syncthreads();
#pragma unroll
        for (int q = 0; q < 4; q++) {
            float tot = qs[q] + red2[(1 - hh) * 128 + R[q]];
            sc[q] = 1.0f / fmaxf(sqrtf(tot), 1e-12f);
        }
    }
#pragma unroll
    for (int mi = 0; mi < 2; mi++) {
        int rA = row0 + R[2 * mi];
        int rB = row0 + R[2 * mi + 1];
#pragma unroll
        for (int ni = 0; ni < 8; ni++) {
            int col = n0 + ni * 8 + t * 2;
            float y0 = acc[mi][ni][0] * sc[2 * mi];
            float y1 = acc[mi][ni][1] * sc[2 * mi];
            float y2 = acc[mi][ni][2] * sc[2 * mi + 1];
            float y3 = acc[mi][ni][3] * sc[2 * mi + 1];
            if (mode == 0) {
                if (rA < NN)
                    *(uint32_t*)(outh + (size_t)rA * 128 + col) = packh2(y0, y1);
                if (rB < NN)
                    *(uint32_t*)(outh + (size_t)rB * 128 + col) = packh2(y2, y3);
            } else {
                if (rA < NN)
                    *(float2*)(outf + (size_t)rA * 128 + col) = make_float2(y0, y1);
                if (rB < NN)
                    *(float2*)(outf + (size_t)rB * 128 + col) = make_float2(y2, y3);
            }
        }
    }
}

// ---------------- launch --------------------------------------------------------
extern "C" void kernel_launch(void* const* d_in, const int* in_sizes, int n_in,
                              void* d_out, int out_size) {
    const float* x = (const float*)d_in[0];
    const void* ei = d_in[1];

    __half *t0, *t1, *agg16, *wt;
    cudaGetSymbolAddress((void**)&t0, g_t0);
    cudaGetSymbolAddress((void**)&t1, g_t1);
    cudaGetSymbolAddress((void**)&agg16, g_agg16);
    cudaGetSymbolAddress((void**)&wt, g_wt);

    cudaFuncSetAttribute(k_gemm_mma, cudaFuncAttributeMaxDynamicSharedMemorySize, SM_TOTAL);

    const int TB = 256;
    const int EBLK = (EE + TB - 1) / TB;
    const int SCAN_NB = (NN + 1023) / 1024;
    const int NBLK = (NN + TB - 1) / TB;
    const int AGG_BLK = (NN * 32 + TB - 1) / TB;
    const int GEMM_BLK = (NN + 127) / 128;
    const int IH_BLK = (NROWS4 + TB - 1) / TB;

    const float* Wl0 = (const float*)d_in[2], *bl0 = (const float*)d_in[3];
    const float* Wr0 = (const float*)d_in[4], *g0 = (const float*)d_in[5], *b0 = (const float*)d_in[6];
    const float* Wl1 = (const float*)d_in[7], *bl1 = (const float*)d_in[8];
    const float* Wr1 = (const float*)d_in[9], *g1 = (const float*)d_in[10], *b1 = (const float*)d_in[11];
    const float* Wl2 = (const float*)d_in[12], *bl2 = (const float*)d_in[13];
    const float* Wr2 = (const float*)d_in[14], *g2 = (const float*)d_in[15], *b2 = (const float*)d_in[16];

    k_inithist<<<IH_BLK, TB>>>(x, ei);
    k_scan1<<<SCAN_NB, 1024>>>();
    k_scan3b<<<NBLK, TB>>>();
    k_scatter<<<EBLK, TB>>>(ei);
    k_wsplit_all<<<384, TB>>>(Wl0, Wr0, Wl1, Wr1, Wl2, Wr2);

    // layer 0
    k_aggregate<<<AGG_BLK, TB>>>(t0);
    k_gemm_mma<<<GEMM_BLK, TB, SM_TOTAL>>>(agg16, t0, wt, bl0, g0, b0,
                                           nullptr, t1, 0);
    // layer 1
    k_aggregate<<<AGG_BLK, TB>>>(t1);
    k_gemm_mma<<<GEMM_BLK, TB, SM_TOTAL>>>(agg16, t1, wt + 32768, bl1, g1, b1,
                                           nullptr, t0, 0);
    // layer 2
    k_aggregate<<<AGG_BLK, TB>>>(t0);
    k_gemm_mma<<<GEMM_BLK, TB, SM_TOTAL>>>(agg16, t0, wt + 65536, bl2, g2, b2,
                                           (float*)d_out, nullptr, 1);
}